// round 14
// baseline (speedup 1.0000x reference)
#include <cuda_runtime.h>
#include <math.h>

// Problem dims
#define Bn   64
#define Tn   1024
#define In   128
#define Hn   512
#define HHn  256
#define On   10

// Scan config: 4 group-pairs x 16 H-slices = 64 CTAs, each runs 2 batch groups
#define NG    8
#define NPAIR 4
#define NSL   16
#define BPG   8      // batch rows per group
#define JS    32     // H cols per slice
#define MS    16     // HH cols per slice
#define NTHR  256

// SMEM (floats)
#define WT1H_F  (512*17)
#define HS_F    (512*8)
#define HID_F   (256*8)
#define RED_F   2304
#define SMEM_FLOATS (WT1H_F + 2*HS_F + 2*HID_F + 2*RED_F + 96)
#define SMEM_BYTES  (SMEM_FLOATS * 4)

typedef unsigned long long ull;

// Static scratch
__device__ float    g_xh[(size_t)Bn*Tn*Hn];     // xp in, hs out (in-place)
__device__ float    g_xtau[(size_t)Bn*Tn*HHn];
__device__ float    g_hx[NG*512*8];             // h exchange, pair-packed
__device__ float    g_hidx[NG*256*8];           // hid exchange, pair-packed
__device__ float    g_Wcomb[In*HHn];
__device__ float    g_bcomb[HHn];
__device__ unsigned g_bar[NG];

__global__ void init_kernel() {
    if (threadIdx.x < NG) g_bar[threadIdx.x] = 0u;
}

// f32x2 packed helpers (FFMA2 via PTX)
__device__ __forceinline__ ull ffma2(ull a, ull b, ull c) {
    ull d;
    asm("fma.rn.f32x2 %0, %1, %2, %3;" : "=l"(d) : "l"(a), "l"(b), "l"(c));
    return d;
}
__device__ __forceinline__ ull splat2(float w) {
    ull d;
    asm("mov.b64 %0, {%1, %1};" : "=l"(d) : "f"(w));
    return d;
}
__device__ __forceinline__ float2 unpk(ull v) {
    float2 r;
    asm("mov.b64 {%0, %1}, %2;" : "=f"(r.x), "=f"(r.y) : "l"(v));
    return r;
}

// ---------------------------------------------------------------------------
// W_comb = W_in @ W_tau1[:H,:], b_comb = b_in @ W_tau1[:H,:] + b_tau1
// ---------------------------------------------------------------------------
__global__ void __launch_bounds__(256) wcomb_kernel(
    const float* __restrict__ W_in, const float* __restrict__ b_in,
    const float* __restrict__ W_tau1, const float* __restrict__ b_tau1,
    float* __restrict__ W_comb, float* __restrict__ b_comb)
{
    const int m = threadIdx.x;
    const int i = blockIdx.x;
    if (i < In) {
        float acc = 0.f;
        for (int k = 0; k < Hn; k += 4) {
            float4 a = *(const float4*)(W_in + i * Hn + k);
            acc = fmaf(a.x, W_tau1[(k + 0) * HHn + m], acc);
            acc = fmaf(a.y, W_tau1[(k + 1) * HHn + m], acc);
            acc = fmaf(a.z, W_tau1[(k + 2) * HHn + m], acc);
            acc = fmaf(a.w, W_tau1[(k + 3) * HHn + m], acc);
        }
        W_comb[i * HHn + m] = acc;
    } else {
        float acc = b_tau1[m];
        for (int k = 0; k < Hn; ++k)
            acc = fmaf(b_in[k], W_tau1[k * HHn + m], acc);
        b_comb[m] = acc;
    }
}

// ---------------------------------------------------------------------------
// Tiled fp32 GEMM + bias (precompute)
// ---------------------------------------------------------------------------
__global__ void __launch_bounds__(256) gemm_bias_kernel(
    const float* __restrict__ A, const float* __restrict__ Bw,
    const float* __restrict__ bias, float* __restrict__ C,
    int M, int N, int K)
{
    __shared__ float As[16][128];
    __shared__ float Bs[16][64];

    const int tid = threadIdx.x;
    const int tx  = tid & 15;
    const int ty  = tid >> 4;
    const int bm  = blockIdx.y * 128;
    const int bn  = blockIdx.x * 64;

    float acc[8][4];
#pragma unroll
    for (int i = 0; i < 8; ++i)
#pragma unroll
        for (int j = 0; j < 4; ++j) acc[i][j] = 0.f;

    const int lar = tid >> 2;
    const int lac = (tid & 3) * 4;
    const int lbr = tid >> 4;
    const int lbc = (tid & 15) * 4;

    for (int k0 = 0; k0 < K; k0 += 16) {
#pragma unroll
        for (int l = 0; l < 2; ++l) {
            int r = lar + l * 64;
            float4 a4 = *(const float4*)&A[(size_t)(bm + r) * K + k0 + lac];
            As[lac + 0][r] = a4.x;
            As[lac + 1][r] = a4.y;
            As[lac + 2][r] = a4.z;
            As[lac + 3][r] = a4.w;
        }
        *(float4*)&Bs[lbr][lbc] = *(const float4*)&Bw[(size_t)(k0 + lbr) * N + bn + lbc];
        __syncthreads();

#pragma unroll
        for (int kk = 0; kk < 16; ++kk) {
            float arv[8], brv[4];
#pragma unroll
            for (int i = 0; i < 8; ++i) arv[i] = As[kk][ty * 8 + i];
#pragma unroll
            for (int j = 0; j < 4; ++j) brv[j] = Bs[kk][tx * 4 + j];
#pragma unroll
            for (int i = 0; i < 8; ++i)
#pragma unroll
                for (int j = 0; j < 4; ++j)
                    acc[i][j] = fmaf(arv[i], brv[j], acc[i][j]);
        }
        __syncthreads();
    }

    float4 bv = *(const float4*)&bias[bn + tx * 4];
#pragma unroll
    for (int i = 0; i < 8; ++i) {
        float4 o;
        o.x = acc[i][0] + bv.x;
        o.y = acc[i][1] + bv.y;
        o.z = acc[i][2] + bv.z;
        o.w = acc[i][3] + bv.w;
        *(float4*)&C[(size_t)(bm + ty * 8 + i) * N + bn + tx * 4] = o;
    }
}

// ---------------------------------------------------------------------------
// Persistent scan kernel: 64 CTAs, each interleaves 2 independent batch
// groups (A,B). W_rec/W_tau2 slices live in registers; W_tau1h in SMEM.
// Cross-CTA exchange: st.cg publish + tid0 fence/arrive, ld.cg consume.
// ---------------------------------------------------------------------------

#define WT1H_PHASE(HS, RED) {                                               \
    const float* wp = Wt1h_s + (kc16 * 32) * 17 + m16;                      \
    const float* hp = (HS) + (kc16 * 32) * 8;                               \
    ull a01 = 0, a23 = 0, a45 = 0, a67 = 0;                                 \
    _Pragma("unroll")                                                       \
    for (int j = 0; j < 32; ++j) {                                          \
        ull w2 = splat2(wp[j * 17]);                                        \
        ulonglong2 p0 = *(const ulonglong2*)(hp + j * 8);                   \
        ulonglong2 p1 = *(const ulonglong2*)(hp + j * 8 + 4);               \
        a01 = ffma2(w2, p0.x, a01); a23 = ffma2(w2, p0.y, a23);             \
        a45 = ffma2(w2, p1.x, a45); a67 = ffma2(w2, p1.y, a67); }           \
    float* rb = (RED) + kc16 * 144 + m16 * 9;                               \
    float2 q0 = unpk(a01), q1 = unpk(a23), q2 = unpk(a45), q3 = unpk(a67);  \
    rb[0] = q0.x; rb[1] = q0.y; rb[2] = q1.x; rb[3] = q1.y;                 \
    rb[4] = q2.x; rb[5] = q2.y; rb[6] = q3.x; rb[7] = q3.y; }

#define REC_PHASE(HS, RED) {                                                \
    const float* hp = (HS) + (kc8 * 64) * 8;                                \
    ull a01 = 0, a23 = 0, a45 = 0, a67 = 0;                                 \
    _Pragma("unroll")                                                       \
    for (int j = 0; j < 64; ++j) {                                          \
        ull w2 = splat2(wrec[j]);                                           \
        ulonglong2 p0 = *(const ulonglong2*)(hp + j * 8);                   \
        ulonglong2 p1 = *(const ulonglong2*)(hp + j * 8 + 4);               \
        a01 = ffma2(w2, p0.x, a01); a23 = ffma2(w2, p0.y, a23);             \
        a45 = ffma2(w2, p1.x, a45); a67 = ffma2(w2, p1.y, a67); }           \
    float* rb = (RED) + kc8 * 288 + c8 * 9;                                 \
    float2 q0 = unpk(a01), q1 = unpk(a23), q2 = unpk(a45), q3 = unpk(a67);  \
    rb[0] = q0.x; rb[1] = q0.y; rb[2] = q1.x; rb[3] = q1.y;                 \
    rb[4] = q2.x; rb[5] = q2.y; rb[6] = q3.x; rb[7] = q3.y; }

#define WT2_PHASE(HIDS, RED) {                                              \
    const float* hp = (HIDS) + (kc8 * 32) * 8;                              \
    ull a01 = 0, a23 = 0, a45 = 0, a67 = 0;                                 \
    _Pragma("unroll")                                                       \
    for (int j = 0; j < 32; ++j) {                                          \
        ull w2 = splat2(wt2r[j]);                                           \
        ulonglong2 p0 = *(const ulonglong2*)(hp + j * 8);                   \
        ulonglong2 p1 = *(const ulonglong2*)(hp + j * 8 + 4);               \
        a01 = ffma2(w2, p0.x, a01); a23 = ffma2(w2, p0.y, a23);             \
        a45 = ffma2(w2, p1.x, a45); a67 = ffma2(w2, p1.y, a67); }           \
    float* rb = (RED) + kc8 * 288 + c8 * 9;                                 \
    float2 q0 = unpk(a01), q1 = unpk(a23), q2 = unpk(a45), q3 = unpk(a67);  \
    rb[0] = q0.x; rb[1] = q0.y; rb[2] = q1.x; rb[3] = q1.y;                 \
    rb[4] = q2.x; rb[5] = q2.y; rb[6] = q3.x; rb[7] = q3.y; }

// fence + relaxed arrive by tid0 (cumulativity via the preceding bar.sync)
#define ARRIVE(BARP) if (tid == 0) { __threadfence(); atomicAdd((BARP), 1u); }
#define SPIN(BARP, TGT) if (tid == 0) {                                     \
    while (((volatile unsigned*)(BARP))[0] < (TGT)) { } }

__global__ void __launch_bounds__(NTHR, 1) recur_kernel(
    const float* __restrict__ W_rec, const float* __restrict__ bias,
    const float* __restrict__ W_tau1, const float* __restrict__ W_tau2,
    const float* __restrict__ b_tau2)
{
    extern __shared__ float sm[];
    float* Wt1h_s = sm;                       // [512][17]
    float* hsA    = Wt1h_s + WT1H_F;          // [512][8] pair-packed
    float* hsB    = hsA + HS_F;
    float* hidA_s = hsB + HS_F;               // [256][8]
    float* hidB_s = hidA_s + HID_F;
    float* redA   = hidB_s + HID_F;           // [2304]
    float* redB   = redA + RED_F;
    float* bias_s = redB + RED_F;             // [32]
    float* bt2_s  = bias_s + 32;              // [32]

    const int tid  = threadIdx.x;
    const int pair = blockIdx.x >> 4;
    const int sl   = blockIdx.x & 15;
    const int js   = sl * JS;
    const int ms   = sl * MS;
    const int gA   = pair * 2, gB = gA + 1;
    const int bgA  = gA * BPG, bgB = gB * BPG;

    const int kc8  = tid >> 5, c8  = tid & 31;   // rec/wt2 map (also output owner r_o=kc8, c_o=c8)
    const int kc16 = tid >> 4, m16 = tid & 15;   // wt1h map (also hid owner r_h=kc16<8?, m_h=m16)

    // ---- weight registers (shared by groups A and B) ----
    float wrec[64], wt2r[32];
#pragma unroll
    for (int j = 0; j < 64; ++j)
        wrec[j] = __ldg(&W_rec[(js + c8) * Hn + kc8 * 64 + j]);
#pragma unroll
    for (int j = 0; j < 32; ++j)
        wt2r[j] = __ldg(&W_tau2[(kc8 * 32 + j) * Hn + js + c8]);

    for (int idx = tid; idx < Hn * MS; idx += NTHR) {
        int m = idx & 15, k = idx >> 4;
        Wt1h_s[k * 17 + m] = W_tau1[(Hn + k) * HHn + ms + m];
    }
    if (tid < 32) {
        bias_s[tid] = bias[js + tid];
        bt2_s[tid]  = b_tau2[js + tid];
    }
    for (int i = tid; i < HS_F; i += NTHR) { hsA[i] = 0.f; hsB[i] = 0.f; }
    __syncthreads();

    unsigned tgA = 0, tgB = 0;
    unsigned* barA = &g_bar[gA];
    unsigned* barB = &g_bar[gB];
    float* hxA   = g_hx   + gA * (512 * 8);
    float* hxB   = g_hx   + gB * (512 * 8);
    float* hidxA = g_hidx + gA * (256 * 8);
    float* hidxB = g_hidx + gB * (256 * 8);

    for (int t = 0; t < Tn; ++t) {
        // per-step input prefetch
        float xpA = __ldg(&g_xh[((size_t)(bgA + kc8) * Tn + t) * Hn + js + c8]);
        float xpB = __ldg(&g_xh[((size_t)(bgB + kc8) * Tn + t) * Hn + js + c8]);
        float xtA = 0.f, xtB = 0.f;
        if (tid < 128) {
            xtA = __ldg(&g_xtau[((size_t)(bgA + kc16) * Tn + t) * HHn + ms + m16]);
            xtB = __ldg(&g_xtau[((size_t)(bgB + kc16) * Tn + t) * HHn + ms + m16]);
        }

        // -------- A1: wt1h A, publish hidA, arrive A.b1 --------
        WT1H_PHASE(hsA, redA);
        __syncthreads();                                  // S1
        if (tid < 128) {
            float s = xtA;
#pragma unroll
            for (int kc = 0; kc < 16; ++kc) s += redA[kc * 144 + m16 * 9 + kc16];
            __stcg(&hidxA[(ms + m16) * 8 + kc16], fmaxf(s, 0.f));
        }
        __syncthreads();                                  // S2
        ARRIVE(barA);

        // -------- B1: wt1h B, publish hidB, arrive B.b1 --------
        WT1H_PHASE(hsB, redB);
        __syncthreads();                                  // S3
        if (tid < 128) {
            float s = xtB;
#pragma unroll
            for (int kc = 0; kc < 16; ++kc) s += redB[kc * 144 + m16 * 9 + kc16];
            __stcg(&hidxB[(ms + m16) * 8 + kc16], fmaxf(s, 0.f));
        }
        __syncthreads();                                  // S4
        ARRIVE(barB);

        // -------- A2: rec A --------
        REC_PHASE(hsA, redA);
        __syncthreads();                                  // S5
        float accA = 0.f;
#pragma unroll
        for (int kc = 0; kc < 8; ++kc) accA += redA[kc * 288 + c8 * 9 + kc8];
        tgA += NSL;
        SPIN(barA, tgA);
        __syncthreads();                                  // S6
        {   // stage hidA (ld.cg, fully coalesced)
            float4 v0 = __ldcg((const float4*)hidxA + tid);
            float4 v1 = __ldcg((const float4*)hidxA + 256 + tid);
            *((float4*)hidA_s + tid)       = v0;
            *((float4*)hidA_s + 256 + tid) = v1;
        }

        // -------- B2: rec B (hides hidA staging latency) --------
        REC_PHASE(hsB, redB);
        __syncthreads();                                  // S7
        float accB = 0.f;
#pragma unroll
        for (int kc = 0; kc < 8; ++kc) accB += redB[kc * 288 + c8 * 9 + kc8];

        // -------- A3: wt2 A + epilogue A --------
        WT2_PHASE(hidA_s, redA);
        __syncthreads();                                  // S8
        {
            float tpre = bt2_s[c8];
#pragma unroll
            for (int kc = 0; kc < 8; ++kc) tpre += redA[kc * 288 + c8 * 9 + kc8];
            float tau  = 5.0f + 45.0f / (1.0f + expf(-tpre));
            float drv  = tanhf(xpA + accA + bias_s[c8]);
            float hold = hsA[(js + c8) * 8 + kc8];
            float hnew = hold + (drv - hold) / tau;
            g_xh[((size_t)(bgA + kc8) * Tn + t) * Hn + js + c8] = hnew;
            __stcg(&hxA[(js + c8) * 8 + kc8], hnew);
        }
        __syncthreads();                                  // S9
        ARRIVE(barA);
        tgB += NSL;
        SPIN(barB, tgB);
        __syncthreads();                                  // S10
        {   // stage hidB
            float4 v0 = __ldcg((const float4*)hidxB + tid);
            float4 v1 = __ldcg((const float4*)hidxB + 256 + tid);
            *((float4*)hidB_s + tid)       = v0;
            *((float4*)hidB_s + 256 + tid) = v1;
        }
        __syncthreads();                                  // S11

        // -------- B3: wt2 B + epilogue B --------
        WT2_PHASE(hidB_s, redB);
        __syncthreads();                                  // S12
        {
            float tpre = bt2_s[c8];
#pragma unroll
            for (int kc = 0; kc < 8; ++kc) tpre += redB[kc * 288 + c8 * 9 + kc8];
            float tau  = 5.0f + 45.0f / (1.0f + expf(-tpre));
            float drv  = tanhf(xpB + accB + bias_s[c8]);
            float hold = hsB[(js + c8) * 8 + kc8];
            float hnew = hold + (drv - hold) / tau;
            g_xh[((size_t)(bgB + kc8) * Tn + t) * Hn + js + c8] = hnew;
            __stcg(&hxB[(js + c8) * 8 + kc8], hnew);
        }
        __syncthreads();                                  // S13
        ARRIVE(barB);

        // -------- reload h for next step --------
        tgA += NSL;
        SPIN(barA, tgA);
        __syncthreads();                                  // S14
        {
            float4 a0 = __ldcg((const float4*)hxA + tid);
            float4 a1 = __ldcg((const float4*)hxA + 256 + tid);
            float4 a2 = __ldcg((const float4*)hxA + 512 + tid);
            float4 a3 = __ldcg((const float4*)hxA + 768 + tid);
            *((float4*)hsA + tid)       = a0;
            *((float4*)hsA + 256 + tid) = a1;
            *((float4*)hsA + 512 + tid) = a2;
            *((float4*)hsA + 768 + tid) = a3;
        }
        tgB += NSL;
        SPIN(barB, tgB);
        __syncthreads();                                  // S15
        {
            float4 a0 = __ldcg((const float4*)hxB + tid);
            float4 a1 = __ldcg((const float4*)hxB + 256 + tid);
            float4 a2 = __ldcg((const float4*)hxB + 512 + tid);
            float4 a3 = __ldcg((const float4*)hxB + 768 + tid);
            *((float4*)hsB + tid)       = a0;
            *((float4*)hsB + 256 + tid) = a1;
            *((float4*)hsB + 512 + tid) = a2;
            *((float4*)hsB + 768 + tid) = a3;
        }
        __syncthreads();                                  // S16
    }
}

// ---------------------------------------------------------------------------
// out[r, :] = hs[r, :] @ W_out + b_out ; one warp per row
// ---------------------------------------------------------------------------
__global__ void __launch_bounds__(256) out_kernel(
    const float* __restrict__ hs, const float* __restrict__ W_out,
    const float* __restrict__ b_out, float* __restrict__ out)
{
    __shared__ float Ws[Hn * 11];
    __shared__ float bo[On];
    const int tid = threadIdx.x;
    for (int idx = tid; idx < Hn * On; idx += 256) {
        int k = idx / On, j = idx - k * On;
        Ws[k * 11 + j] = W_out[idx];
    }
    if (tid < On) bo[tid] = b_out[tid];
    __syncthreads();

    const int lane = tid & 31;
    const int wrp  = tid >> 5;
    const int row  = blockIdx.x * 8 + wrp;
    const float* hr = hs + (size_t)row * Hn;

    float a[On];
#pragma unroll
    for (int j = 0; j < On; ++j) a[j] = 0.f;

#pragma unroll
    for (int kk = 0; kk < 16; ++kk) {
        int k = kk * 32 + lane;
        float h = __ldg(hr + k);
#pragma unroll
        for (int j = 0; j < On; ++j) a[j] = fmaf(h, Ws[k * 11 + j], a[j]);
    }
#pragma unroll
    for (int j = 0; j < On; ++j) {
#pragma unroll
        for (int off = 16; off > 0; off >>= 1)
            a[j] += __shfl_xor_sync(0xffffffffu, a[j], off);
    }
    if (lane == 0) {
#pragma unroll
        for (int j = 0; j < On; ++j)
            out[(size_t)row * On + j] = a[j] + bo[j];
    }
}

// ---------------------------------------------------------------------------
extern "C" void kernel_launch(void* const* d_in, const int* in_sizes, int n_in,
                              void* d_out, int out_size)
{
    const float* x      = (const float*)d_in[0];
    const float* W_in   = (const float*)d_in[1];
    const float* b_in   = (const float*)d_in[2];
    const float* W_rec  = (const float*)d_in[3];
    const float* bias   = (const float*)d_in[4];
    const float* W_tau1 = (const float*)d_in[5];
    const float* b_tau1 = (const float*)d_in[6];
    const float* W_tau2 = (const float*)d_in[7];
    const float* b_tau2 = (const float*)d_in[8];
    const float* W_out  = (const float*)d_in[9];
    const float* b_out  = (const float*)d_in[10];
    float* out = (float*)d_out;

    float *xh, *xtau, *wcomb, *bcomb;
    cudaGetSymbolAddress((void**)&xh,    g_xh);
    cudaGetSymbolAddress((void**)&xtau,  g_xtau);
    cudaGetSymbolAddress((void**)&wcomb, g_Wcomb);
    cudaGetSymbolAddress((void**)&bcomb, g_bcomb);

    cudaFuncSetAttribute(recur_kernel,
                         cudaFuncAttributeMaxDynamicSharedMemorySize, SMEM_BYTES);

    init_kernel<<<1, 32>>>();
    wcomb_kernel<<<In + 1, 256>>>(W_in, b_in, W_tau1, b_tau1, wcomb, bcomb);
    gemm_bias_kernel<<<dim3(Hn / 64, (Bn * Tn) / 128), 256>>>(x, W_in, b_in, xh,
                                                              Bn * Tn, Hn, In);
    gemm_bias_kernel<<<dim3(HHn / 64, (Bn * Tn) / 128), 256>>>(x, wcomb, bcomb, xtau,
                                                               Bn * Tn, HHn, In);
    recur_kernel<<<NPAIR * NSL, NTHR, SMEM_BYTES>>>(W_rec, bias, W_tau1, W_tau2, b_tau2);
    out_kernel<<<(Bn * Tn) / 8, 256>>>(xh, W_out, b_out, out);
}

// round 15
// speedup vs baseline: 1.6435x; 1.6435x over previous
#include <cuda_runtime.h>
#include <math.h>

// Problem dims
#define Bn   64
#define Tn   1024
#define In   128
#define Hn   512
#define HHn  256
#define On   10

// Scan config: 8 batch groups x 16 H-slices = 128 CTAs
#define NG    8
#define NSL   16
#define BPG   8      // batch rows per group
#define JS    32     // H cols per slice
#define MS    16     // HH cols per slice
#define NTHR  512

// SMEM (floats)
#define WREC_F  (512*32)       // Wrec_s[k*32+c]
#define WT1H_F  (512*17)       // Wt1h_s[k*17+m]
#define WT2_F   (256*32)       // Wt2_s[k*32+c]
#define HS_F    (512*8)        // h_s[k][r] pair-packed
#define HID_F   (256*8)        // hid_s[k][r]
#define RED_F   4608           // 16*288 == 32*144
#define SMEM_FLOATS (WREC_F + WT1H_F + WT2_F + HS_F + HID_F + RED_F + 96)
#define SMEM_BYTES  (SMEM_FLOATS * 4)

typedef unsigned long long ull;

// Static scratch
__device__ float    g_xh[(size_t)Bn*Tn*Hn];     // xp in, hs out (in-place)
__device__ float    g_xtau[(size_t)Bn*Tn*HHn];
__device__ float    g_hx[NG*512*8];             // h exchange, pair-packed
__device__ float    g_hidx[NG*256*8];           // hid exchange, pair-packed
__device__ float    g_Wcomb[In*HHn];
__device__ float    g_bcomb[HHn];
__device__ unsigned g_bar[NG];

__global__ void init_kernel() {
    if (threadIdx.x < NG) g_bar[threadIdx.x] = 0u;
}

// f32x2 packed helpers (FFMA2 via PTX)
__device__ __forceinline__ ull ffma2(ull a, ull b, ull c) {
    ull d;
    asm("fma.rn.f32x2 %0, %1, %2, %3;" : "=l"(d) : "l"(a), "l"(b), "l"(c));
    return d;
}
__device__ __forceinline__ ull splat2(float w) {
    ull d;
    asm("mov.b64 %0, {%1, %1};" : "=l"(d) : "f"(w));
    return d;
}
__device__ __forceinline__ float2 unpk(ull v) {
    float2 r;
    asm("mov.b64 {%0, %1}, %2;" : "=f"(r.x), "=f"(r.y) : "l"(v));
    return r;
}

// ---------------------------------------------------------------------------
// W_comb = W_in @ W_tau1[:H,:], b_comb = b_in @ W_tau1[:H,:] + b_tau1
// ---------------------------------------------------------------------------
__global__ void __launch_bounds__(256) wcomb_kernel(
    const float* __restrict__ W_in, const float* __restrict__ b_in,
    const float* __restrict__ W_tau1, const float* __restrict__ b_tau1,
    float* __restrict__ W_comb, float* __restrict__ b_comb)
{
    const int m = threadIdx.x;
    const int i = blockIdx.x;
    if (i < In) {
        float acc = 0.f;
        for (int k = 0; k < Hn; k += 4) {
            float4 a = *(const float4*)(W_in + i * Hn + k);
            acc = fmaf(a.x, W_tau1[(k + 0) * HHn + m], acc);
            acc = fmaf(a.y, W_tau1[(k + 1) * HHn + m], acc);
            acc = fmaf(a.z, W_tau1[(k + 2) * HHn + m], acc);
            acc = fmaf(a.w, W_tau1[(k + 3) * HHn + m], acc);
        }
        W_comb[i * HHn + m] = acc;
    } else {
        float acc = b_tau1[m];
        for (int k = 0; k < Hn; ++k)
            acc = fmaf(b_in[k], W_tau1[k * HHn + m], acc);
        b_comb[m] = acc;
    }
}

// ---------------------------------------------------------------------------
// Tiled fp32 GEMM + bias (precompute)
// ---------------------------------------------------------------------------
__global__ void __launch_bounds__(256) gemm_bias_kernel(
    const float* __restrict__ A, const float* __restrict__ Bw,
    const float* __restrict__ bias, float* __restrict__ C,
    int M, int N, int K)
{
    __shared__ float As[16][128];
    __shared__ float Bs[16][64];

    const int tid = threadIdx.x;
    const int tx  = tid & 15;
    const int ty  = tid >> 4;
    const int bm  = blockIdx.y * 128;
    const int bn  = blockIdx.x * 64;

    float acc[8][4];
#pragma unroll
    for (int i = 0; i < 8; ++i)
#pragma unroll
        for (int j = 0; j < 4; ++j) acc[i][j] = 0.f;

    const int lar = tid >> 2;
    const int lac = (tid & 3) * 4;
    const int lbr = tid >> 4;
    const int lbc = (tid & 15) * 4;

    for (int k0 = 0; k0 < K; k0 += 16) {
#pragma unroll
        for (int l = 0; l < 2; ++l) {
            int r = lar + l * 64;
            float4 a4 = *(const float4*)&A[(size_t)(bm + r) * K + k0 + lac];
            As[lac + 0][r] = a4.x;
            As[lac + 1][r] = a4.y;
            As[lac + 2][r] = a4.z;
            As[lac + 3][r] = a4.w;
        }
        *(float4*)&Bs[lbr][lbc] = *(const float4*)&Bw[(size_t)(k0 + lbr) * N + bn + lbc];
        __syncthreads();

#pragma unroll
        for (int kk = 0; kk < 16; ++kk) {
            float arv[8], brv[4];
#pragma unroll
            for (int i = 0; i < 8; ++i) arv[i] = As[kk][ty * 8 + i];
#pragma unroll
            for (int j = 0; j < 4; ++j) brv[j] = Bs[kk][tx * 4 + j];
#pragma unroll
            for (int i = 0; i < 8; ++i)
#pragma unroll
                for (int j = 0; j < 4; ++j)
                    acc[i][j] = fmaf(arv[i], brv[j], acc[i][j]);
        }
        __syncthreads();
    }

    float4 bv = *(const float4*)&bias[bn + tx * 4];
#pragma unroll
    for (int i = 0; i < 8; ++i) {
        float4 o;
        o.x = acc[i][0] + bv.x;
        o.y = acc[i][1] + bv.y;
        o.z = acc[i][2] + bv.z;
        o.w = acc[i][3] + bv.w;
        *(float4*)&C[(size_t)(bm + ty * 8 + i) * N + bn + tx * 4] = o;
    }
}

// ---------------------------------------------------------------------------
// Persistent scan kernel. 128 CTAs x 512 threads (4 warps/SMSP for latency
// hiding). Weights SMEM-resident; 8-row register tile, packed f32x2 FFMA;
// h/hid exchanged through L2 pair-packed with split arrive/wait barriers.
// ---------------------------------------------------------------------------
__global__ void __launch_bounds__(NTHR, 1) recur_kernel(
    const float* __restrict__ W_rec, const float* __restrict__ bias,
    const float* __restrict__ W_tau1, const float* __restrict__ W_tau2,
    const float* __restrict__ b_tau2)
{
    extern __shared__ float sm[];
    float* Wrec_s = sm;                      // [512][32]
    float* Wt1h_s = Wrec_s + WREC_F;         // [512][17]
    float* Wt2_s  = Wt1h_s + WT1H_F;         // [256][32]
    float* h_s    = Wt2_s + WT2_F;           // [512][8]
    float* hid_s  = h_s + HS_F;              // [256][8]
    float* red    = hid_s + HID_F;           // [4608]
    float* bias_s = red + RED_F;             // [32]
    float* bt2_s  = bias_s + 32;             // [32]

    const int tid  = threadIdx.x;
    const int g    = blockIdx.x >> 4;
    const int sl   = blockIdx.x & 15;
    const int js   = sl * JS;
    const int ms   = sl * MS;
    const int bg0  = g * BPG;

    // phase maps
    const int kcr = tid >> 5;                 // 0..15  rec/wt2 k-chunk
    const int c8  = tid & 31;                 // col 0..31
    const int kcw = tid >> 4;                 // 0..31  wt1h k-chunk
    const int m16 = tid & 15;                 // m 0..15
    // owners
    const int r_o = (tid >> 5) & 7;           // output row (valid tid<256)
    const int c_o = tid & 31;
    const int r_h = (tid >> 4) & 7;           // hid row (valid tid<128)
    const int m_h = tid & 15;

    // ---- one-time weight staging ----
    for (int idx = tid; idx < Hn * JS; idx += NTHR) {
        int c = idx & 31, k = idx >> 5;
        Wrec_s[k * 32 + c] = W_rec[(js + c) * Hn + k];
    }
    for (int idx = tid; idx < Hn * MS; idx += NTHR) {
        int m = idx & 15, k = idx >> 4;
        Wt1h_s[k * 17 + m] = W_tau1[(Hn + k) * HHn + ms + m];
    }
    for (int idx = tid; idx < HHn * JS; idx += NTHR) {
        int c = idx & 31, k = idx >> 5;
        Wt2_s[k * 32 + c] = W_tau2[k * Hn + js + c];
    }
    if (tid < 32) {
        bias_s[tid] = bias[js + tid];
        bt2_s[tid]  = b_tau2[js + tid];
    }
    for (int i = tid; i < HS_F; i += NTHR) h_s[i] = 0.f;   // h0 = 0
    __syncthreads();

    unsigned tgt = 0;
    unsigned* barp = &g_bar[g];
    float* hx   = g_hx   + g * (512 * 8);
    float* hidx = g_hidx + g * (256 * 8);

    // initial input prefetch (t = 0)
    float xp_v = 0.f, xtau_v = 0.f;
    if (tid < 256)
        xp_v = __ldg(&g_xh[((size_t)(bg0 + r_o) * Tn + 0) * Hn + js + c_o]);
    if (tid < 128)
        xtau_v = __ldg(&g_xtau[((size_t)(bg0 + r_h) * Tn + 0) * HHn + ms + m_h]);

    for (int t = 0; t < Tn; ++t) {
        // ---- wt1h partials: thread (m16, kcw), 16 k each ----
        {
            const float* wp = Wt1h_s + (kcw * 16) * 17 + m16;
            const float* hp = h_s + (kcw * 16) * 8;
            ull a01 = 0, a23 = 0, a45 = 0, a67 = 0;
#pragma unroll
            for (int j = 0; j < 16; ++j) {
                ull w2 = splat2(wp[j * 17]);
                ulonglong2 p0 = *(const ulonglong2*)(hp + j * 8);
                ulonglong2 p1 = *(const ulonglong2*)(hp + j * 8 + 4);
                a01 = ffma2(w2, p0.x, a01); a23 = ffma2(w2, p0.y, a23);
                a45 = ffma2(w2, p1.x, a45); a67 = ffma2(w2, p1.y, a67);
            }
            float* rb = red + kcw * 144 + m16 * 9;
            float2 q0 = unpk(a01), q1 = unpk(a23), q2 = unpk(a45), q3 = unpk(a67);
            rb[0] = q0.x; rb[1] = q0.y; rb[2] = q1.x; rb[3] = q1.y;
            rb[4] = q2.x; rb[5] = q2.y; rb[6] = q3.x; rb[7] = q3.y;
        }
        __syncthreads();
        if (tid < 128) {
            float s = xtau_v;
#pragma unroll
            for (int kc = 0; kc < 32; ++kc)
                s += red[kc * 144 + m_h * 9 + r_h];
            __stcg(&hidx[(ms + m_h) * 8 + r_h], fmaxf(s, 0.f));
        }
        __syncthreads();
        if (tid == 0) { __threadfence(); atomicAdd(barp, 1u); }  // arrive bar1
        tgt += NSL;

        // ---- rec partials: thread (c8, kcr), 32 k each (hides bar1) ----
        {
            const float* wp = Wrec_s + (kcr * 32) * 32 + c8;
            const float* hp = h_s + (kcr * 32) * 8;
            ull a01 = 0, a23 = 0, a45 = 0, a67 = 0;
#pragma unroll 8
            for (int j = 0; j < 32; ++j) {
                ull w2 = splat2(wp[j * 32]);
                ulonglong2 p0 = *(const ulonglong2*)(hp + j * 8);
                ulonglong2 p1 = *(const ulonglong2*)(hp + j * 8 + 4);
                a01 = ffma2(w2, p0.x, a01); a23 = ffma2(w2, p0.y, a23);
                a45 = ffma2(w2, p1.x, a45); a67 = ffma2(w2, p1.y, a67);
            }
            float* rb = red + kcr * 288 + c8 * 9;
            float2 q0 = unpk(a01), q1 = unpk(a23), q2 = unpk(a45), q3 = unpk(a67);
            rb[0] = q0.x; rb[1] = q0.y; rb[2] = q1.x; rb[3] = q1.y;
            rb[4] = q2.x; rb[5] = q2.y; rb[6] = q3.x; rb[7] = q3.y;
        }
        __syncthreads();
        float acc_rec = 0.f;
        if (tid < 256) {
#pragma unroll
            for (int kc = 0; kc < 16; ++kc)
                acc_rec += red[kc * 288 + c_o * 9 + r_o];
        }
        if (tid == 0) {                               // wait bar1
            while (((volatile unsigned*)barp)[0] < tgt) { }
        }
        __syncthreads();

        // stage hid (coalesced, pair-packed already): 512 float4
        {
            float4 v = __ldcg((const float4*)hidx + tid);
            *((float4*)hid_s + tid) = v;
        }
        __syncthreads();

        // ---- wt2 partials: thread (c8, kcr), 16 k each ----
        {
            const float* wp = Wt2_s + (kcr * 16) * 32 + c8;
            const float* hp = hid_s + (kcr * 16) * 8;
            ull a01 = 0, a23 = 0, a45 = 0, a67 = 0;
#pragma unroll
            for (int j = 0; j < 16; ++j) {
                ull w2 = splat2(wp[j * 32]);
                ulonglong2 p0 = *(const ulonglong2*)(hp + j * 8);
                ulonglong2 p1 = *(const ulonglong2*)(hp + j * 8 + 4);
                a01 = ffma2(w2, p0.x, a01); a23 = ffma2(w2, p0.y, a23);
                a45 = ffma2(w2, p1.x, a45); a67 = ffma2(w2, p1.y, a67);
            }
            float* rb = red + kcr * 288 + c8 * 9;
            float2 q0 = unpk(a01), q1 = unpk(a23), q2 = unpk(a45), q3 = unpk(a67);
            rb[0] = q0.x; rb[1] = q0.y; rb[2] = q1.x; rb[3] = q1.y;
            rb[4] = q2.x; rb[5] = q2.y; rb[6] = q3.x; rb[7] = q3.y;
        }
        __syncthreads();

        // ---- epilogue: tau, drive, Euler update, publish ----
        if (tid < 256) {
            float tpre = bt2_s[c_o];
#pragma unroll
            for (int kc = 0; kc < 16; ++kc)
                tpre += red[kc * 288 + c_o * 9 + r_o];
            float tau  = 5.0f + 45.0f / (1.0f + expf(-tpre));
            float drv  = tanhf(xp_v + acc_rec + bias_s[c_o]);
            float hold = h_s[(js + c_o) * 8 + r_o];
            float hnew = hold + (drv - hold) / tau;
            g_xh[((size_t)(bg0 + r_o) * Tn + t) * Hn + js + c_o] = hnew;  // hs out
            __stcg(&hx[(js + c_o) * 8 + r_o], hnew);                      // exchange
        }
        __syncthreads();
        if (tid == 0) { __threadfence(); atomicAdd(barp, 1u); }  // arrive bar2
        tgt += NSL;

        // prefetch next-step inputs while bar2 completes
        if (t + 1 < Tn) {
            if (tid < 256)
                xp_v = __ldg(&g_xh[((size_t)(bg0 + r_o) * Tn + (t + 1)) * Hn + js + c_o]);
            if (tid < 128)
                xtau_v = __ldg(&g_xtau[((size_t)(bg0 + r_h) * Tn + (t + 1)) * HHn + ms + m_h]);
        }

        if (tid == 0) {                               // wait bar2
            while (((volatile unsigned*)barp)[0] < tgt) { }
        }
        __syncthreads();

        // reload full h (1024 float4, 2 per thread)
        {
            float4 a0 = __ldcg((const float4*)hx + tid);
            float4 a1 = __ldcg((const float4*)hx + NTHR + tid);
            *((float4*)h_s + tid)        = a0;
            *((float4*)h_s + NTHR + tid) = a1;
        }
        __syncthreads();
    }
}

// ---------------------------------------------------------------------------
// out[r, :] = hs[r, :] @ W_out + b_out ; one warp per row
// ---------------------------------------------------------------------------
__global__ void __launch_bounds__(256) out_kernel(
    const float* __restrict__ hs, const float* __restrict__ W_out,
    const float* __restrict__ b_out, float* __restrict__ out)
{
    __shared__ float Ws[Hn * 11];
    __shared__ float bo[On];
    const int tid = threadIdx.x;
    for (int idx = tid; idx < Hn * On; idx += 256) {
        int k = idx / On, j = idx - k * On;
        Ws[k * 11 + j] = W_out[idx];
    }
    if (tid < On) bo[tid] = b_out[tid];
    __syncthreads();

    const int lane = tid & 31;
    const int wrp  = tid >> 5;
    const int row  = blockIdx.x * 8 + wrp;
    const float* hr = hs + (size_t)row * Hn;

    float a[On];
#pragma unroll
    for (int j = 0; j < On; ++j) a[j] = 0.f;

#pragma unroll
    for (int kk = 0; kk < 16; ++kk) {
        int k = kk * 32 + lane;
        float h = __ldg(hr + k);
#pragma unroll
        for (int j = 0; j < On; ++j) a[j] = fmaf(h, Ws[k * 11 + j], a[j]);
    }
#pragma unroll
    for (int j = 0; j < On; ++j) {
#pragma unroll
        for (int off = 16; off > 0; off >>= 1)
            a[j] += __shfl_xor_sync(0xffffffffu, a[j], off);
    }
    if (lane == 0) {
#pragma unroll
        for (int j = 0; j < On; ++j)
            out[(size_t)row * On + j] = a[j] + bo[j];
    }
}

// ---------------------------------------------------------------------------
extern "C" void kernel_launch(void* const* d_in, const int* in_sizes, int n_in,
                              void* d_out, int out_size)
{
    const float* x      = (const float*)d_in[0];
    const float* W_in   = (const float*)d_in[1];
    const float* b_in   = (const float*)d_in[2];
    const float* W_rec  = (const float*)d_in[3];
    const float* bias   = (const float*)d_in[4];
    const float* W_tau1 = (const float*)d_in[5];
    const float* b_tau1 = (const float*)d_in[6];
    const float* W_tau2 = (const float*)d_in[7];
    const float* b_tau2 = (const float*)d_in[8];
    const float* W_out  = (const float*)d_in[9];
    const float* b_out  = (const float*)d_in[10];
    float* out = (float*)d_out;

    float *xh, *xtau, *wcomb, *bcomb;
    cudaGetSymbolAddress((void**)&xh,    g_xh);
    cudaGetSymbolAddress((void**)&xtau,  g_xtau);
    cudaGetSymbolAddress((void**)&wcomb, g_Wcomb);
    cudaGetSymbolAddress((void**)&bcomb, g_bcomb);

    cudaFuncSetAttribute(recur_kernel,
                         cudaFuncAttributeMaxDynamicSharedMemorySize, SMEM_BYTES);

    init_kernel<<<1, 32>>>();
    wcomb_kernel<<<In + 1, 256>>>(W_in, b_in, W_tau1, b_tau1, wcomb, bcomb);
    gemm_bias_kernel<<<dim3(Hn / 64, (Bn * Tn) / 128), 256>>>(x, W_in, b_in, xh,
                                                              Bn * Tn, Hn, In);
    gemm_bias_kernel<<<dim3(HHn / 64, (Bn * Tn) / 128), 256>>>(x, wcomb, bcomb, xtau,
                                                               Bn * Tn, HHn, In);
    recur_kernel<<<NG * NSL, NTHR, SMEM_BYTES>>>(W_rec, bias, W_tau1, W_tau2, b_tau2);
    out_kernel<<<(Bn * Tn) / 8, 256>>>(xh, W_out, b_out, out);
}